// round 1
// baseline (speedup 1.0000x reference)
#include <cuda_runtime.h>
#include <math.h>

#define BATCH 2
#define SEQ 1024
#define FEAT 80
#define DMODEL 512
#define DSTATE 16
#define DCONV 7
#define HEADDIM 64
#define DINNER 1024
#define NHEADS 16
#define CONVDIM 1056
#define DINPROJ 2096
#define NTOK (BATCH*SEQ)
#define EPSF 1e-5f

// ---------------- scratch (device globals: allocation-free) ----------------
__device__ float g_h[NTOK*DMODEL];
__device__ float g_hn[NTOK*DMODEL];
__device__ float g_zx[2][NTOK*DINPROJ];
__device__ float g_xbc[2][NTOK*CONVDIM];
__device__ float g_dt[2][NTOK*NHEADS];
__device__ float g_dA[2][NTOK*NHEADS];
__device__ float g_y[2][NTOK*DINNER];
__device__ float g_hfin[NTOK*DMODEL];

// ---------------- generic fp32 GEMM: C[M,N] (+)= A[M,K] @ B[K,N] (+bias) ---
// BM=128, BN=64, BK=16, 256 threads, 8x4 per-thread microtile.
// M always multiple of 128, K multiple of 16 & 4-aligned rows; N edge guarded.
template<bool ACCUM, bool BIAS>
__global__ void __launch_bounds__(256) gemm_k(
    const float* __restrict__ A, const float* __restrict__ B,
    const float* __restrict__ bias, float* __restrict__ C,
    int M, int N, int K, long bz, long cz)
{
    B += (long)blockIdx.z * bz;
    C += (long)blockIdx.z * cz;
    __shared__ float As[128][16];
    __shared__ float Bs[16][64];
    const int tid = threadIdx.x;
    const int m0 = blockIdx.y * 128;
    const int n0 = blockIdx.x * 64;
    const int tx = tid & 15, ty = tid >> 4;
    const int ar = tid >> 2, ac = (tid & 3) << 2;
    const int bk = tid >> 4, bn = (tid & 15) << 2;
    const bool nEdge = (n0 + 64 > N);
    float acc[8][4];
    #pragma unroll
    for (int i = 0; i < 8; i++)
        #pragma unroll
        for (int j = 0; j < 4; j++) acc[i][j] = 0.f;

    for (int k0 = 0; k0 < K; k0 += 16) {
        float4 a0 = *(const float4*)(A + (long)(m0 + ar) * K + k0 + ac);
        float4 a1 = *(const float4*)(A + (long)(m0 + ar + 64) * K + k0 + ac);
        *(float4*)&As[ar][ac] = a0;
        *(float4*)&As[ar + 64][ac] = a1;
        if (!nEdge) {
            *(float4*)&Bs[bk][bn] = *(const float4*)(B + (long)(k0 + bk) * N + n0 + bn);
        } else {
            #pragma unroll
            for (int j = 0; j < 4; j++)
                Bs[bk][bn + j] = (n0 + bn + j < N) ? B[(long)(k0 + bk) * N + n0 + bn + j] : 0.f;
        }
        __syncthreads();
        #pragma unroll
        for (int kk = 0; kk < 16; kk++) {
            float av[8], bv[4];
            #pragma unroll
            for (int i = 0; i < 8; i++) av[i] = As[ty * 8 + i][kk];
            #pragma unroll
            for (int j = 0; j < 4; j++) bv[j] = Bs[kk][tx * 4 + j];
            #pragma unroll
            for (int i = 0; i < 8; i++)
                #pragma unroll
                for (int j = 0; j < 4; j++)
                    acc[i][j] += av[i] * bv[j];
        }
        __syncthreads();
    }
    #pragma unroll
    for (int i = 0; i < 8; i++) {
        int m = m0 + ty * 8 + i;
        #pragma unroll
        for (int j = 0; j < 4; j++) {
            int n = n0 + tx * 4 + j;
            if (n < N) {
                long idx = (long)m * N + n;
                float v = acc[i][j];
                if (BIAS) v += bias[n];
                if (ACCUM) v += C[idx];
                C[idx] = v;
            }
        }
    }
}

// ---------------- reductions ----------------
__device__ __forceinline__ float warpSum(float v) {
    #pragma unroll
    for (int o = 16; o; o >>= 1) v += __shfl_down_sync(0xffffffffu, v, o);
    return v;
}

// ---------------- layernorm over DMODEL=512, 256 threads/row ----------------
__global__ void __launch_bounds__(256) layernorm_k(
    const float* __restrict__ in, const float* __restrict__ w,
    const float* __restrict__ b, float* __restrict__ out)
{
    __shared__ float sbuf[8];
    int row = blockIdx.x;
    int tid = threadIdx.x;
    const float* v = in + (long)row * DMODEL;
    float x0 = v[tid], x1 = v[tid + 256];
    float s = warpSum(x0 + x1);
    if ((tid & 31) == 0) sbuf[tid >> 5] = s;
    __syncthreads();
    float mean = 0.f;
    #pragma unroll
    for (int i = 0; i < 8; i++) mean += sbuf[i];
    mean *= (1.f / DMODEL);
    __syncthreads();
    float c0 = x0 - mean, c1 = x1 - mean;
    float ss = warpSum(c0 * c0 + c1 * c1);
    if ((tid & 31) == 0) sbuf[tid >> 5] = ss;
    __syncthreads();
    float var = 0.f;
    #pragma unroll
    for (int i = 0; i < 8; i++) var += sbuf[i];
    var *= (1.f / DMODEL);
    float rs = rsqrtf(var + EPSF);
    out[(long)row * DMODEL + tid]       = c0 * rs * w[tid] + b[tid];
    out[(long)row * DMODEL + tid + 256] = c1 * rs * w[tid + 256] + b[tid + 256];
}

// ---------------- causal depthwise conv (direction-aware) + SiLU -----------
__global__ void __launch_bounds__(128) conv_silu_k(
    const float* __restrict__ convw, const float* __restrict__ convb, int l)
{
    int c = blockIdx.x * 128 + threadIdx.x;
    if (c >= CONVDIM) return;
    int tau = blockIdx.y;
    int dir = blockIdx.z >> 1;
    int b = blockIdx.z & 1;
    const float* w = convw + ((long)((l * 2 + dir) * CONVDIM) + c) * DCONV;
    float acc = convb[(l * 2 + dir) * CONVDIM + c];
    const float* zxp = g_zx[dir];
    #pragma unroll
    for (int k = 0; k < DCONV; k++) {
        int ts = tau - (DCONV - 1) + k;
        if (ts >= 0) {
            int o = dir ? (SEQ - 1 - ts) : ts;
            acc += w[k] * zxp[(long)(b * SEQ + o) * DINPROJ + DINNER + c];
        }
    }
    float s = acc / (1.f + expf(-acc));
    int oo = dir ? (SEQ - 1 - tau) : tau;
    g_xbc[dir][(long)(b * SEQ + oo) * CONVDIM + c] = s;
}

// ---------------- precompute dt (softplus) and dA=exp(dt*A), fully parallel -
__global__ void __launch_bounds__(256) dtprep_k(
    const float* __restrict__ dt_bias, const float* __restrict__ A_log, int l)
{
    int idx = blockIdx.x * 256 + threadIdx.x;
    if (idx >= 2 * NTOK * NHEADS) return;
    int dir = idx / (NTOK * NHEADS);
    int r = idx - dir * (NTOK * NHEADS);
    int h = r & 15;
    int tok = r >> 4;
    float raw = g_zx[dir][(long)tok * DINPROJ + DINNER + CONVDIM + h];
    float xv = raw + dt_bias[(l * 2 + dir) * NHEADS + h];
    float dt = (xv > 20.f) ? xv : log1pf(expf(xv));
    float Av = -expf(A_log[(l * 2 + dir) * NHEADS + h]);
    g_dt[dir][r] = dt;
    g_dA[dir][r] = expf(dt * Av);
}

// ---------------- selective-state scan, chunked 8 steps per barrier --------
// One block per (dir,b,head): 64 threads (one per p). State[16] in registers.
__global__ void __launch_bounds__(64) scan_k(const float* __restrict__ Dp, int l)
{
    int bid = blockIdx.x;
    int dir = bid >> 5;
    int b = (bid >> 4) & 1;
    int h = bid & 15;
    int p = threadIdx.x;
    const float* xbc = g_xbc[dir];
    const float* zx = g_zx[dir];
    const float* dtp = g_dt[dir];
    const float* dAp = g_dA[dir];
    float* yo = g_y[dir];
    const float Dv = Dp[(l * 2 + dir) * NHEADS + h];
    float hs[16];
    #pragma unroll
    for (int n = 0; n < 16; n++) hs[n] = 0.f;
    __shared__ float sB[8][16], sC[8][16], sdt[8], sdA[8];

    for (int t0 = 0; t0 < SEQ; t0 += 8) {
        // cooperative stage of B/C/dt/dA for 8 steps
        #pragma unroll
        for (int i = p; i < 128; i += 64) {
            int tt = i >> 4, n = i & 15;
            int o = dir ? (SEQ - 1 - (t0 + tt)) : (t0 + tt);
            long base = (long)(b * SEQ + o) * CONVDIM + DINNER;
            sB[tt][n] = xbc[base + n];
            sC[tt][n] = xbc[base + DSTATE + n];
        }
        if (p < 8) {
            int o = dir ? (SEQ - 1 - (t0 + p)) : (t0 + p);
            sdt[p] = dtp[(long)(b * SEQ + o) * NHEADS + h];
            sdA[p] = dAp[(long)(b * SEQ + o) * NHEADS + h];
        }
        __syncthreads();

        float xt[8], zt[8];
        int oidx[8];
        #pragma unroll
        for (int j = 0; j < 8; j++) {
            int o = dir ? (SEQ - 1 - (t0 + j)) : (t0 + j);
            oidx[j] = o;
            xt[j] = xbc[(long)(b * SEQ + o) * CONVDIM + h * HEADDIM + p];
            zt[j] = zx[(long)(b * SEQ + o) * DINPROJ + h * HEADDIM + p];
        }
        #pragma unroll
        for (int j = 0; j < 8; j++) {
            float dt = sdt[j], dA = sdA[j];
            float cdt = dt * xt[j];
            float y = 0.f;
            #pragma unroll
            for (int n = 0; n < 16; n++) {
                hs[n] = hs[n] * dA + cdt * sB[j][n];
                y += hs[n] * sC[j][n];
            }
            y += Dv * xt[j];
            float z = zt[j];
            float sil = z / (1.f + expf(-z));
            yo[(long)(b * SEQ + oidx[j]) * DINNER + h * HEADDIM + p] = y * sil;
        }
        __syncthreads();
    }
}

// ---------------- RMS norm over DINNER=1024 (in-place on g_y) --------------
__global__ void __launch_bounds__(256) rmsnorm_k(const float* __restrict__ normw, int l)
{
    __shared__ float sbuf[8];
    int bid = blockIdx.x;
    int dir = bid >> 11;          // NTOK = 2048
    int tok = bid & (NTOK - 1);
    int tid = threadIdx.x;
    float* v = g_y[dir] + (long)tok * DINNER;
    const float* w = normw + (l * 2 + dir) * DINNER;
    float vals[4];
    float ss = 0.f;
    #pragma unroll
    for (int i = 0; i < 4; i++) {
        vals[i] = v[tid + i * 256];
        ss += vals[i] * vals[i];
    }
    ss = warpSum(ss);
    if ((tid & 31) == 0) sbuf[tid >> 5] = ss;
    __syncthreads();
    float tot = 0.f;
    #pragma unroll
    for (int i = 0; i < 8; i++) tot += sbuf[i];
    float rs = rsqrtf(tot * (1.f / DINNER) + EPSF);
    #pragma unroll
    for (int i = 0; i < 4; i++)
        v[tid + i * 256] = vals[i] * rs * w[tid + i * 256];
}

// ---------------- copy final h into d_out tail ----------------
__global__ void __launch_bounds__(256) copy_hfin_k(float* __restrict__ out)
{
    int i = blockIdx.x * 256 + threadIdx.x;
    if (i < NTOK * DMODEL) out[i] = g_hfin[i];
}

// ---------------- launch ----------------
extern "C" void kernel_launch(void* const* d_in, const int* in_sizes, int n_in,
                              void* d_out, int out_size)
{
    const float* x      = (const float*)d_in[0];
    const float* Wpi    = (const float*)d_in[1];
    const float* bpi    = (const float*)d_in[2];
    const float* ln_w   = (const float*)d_in[3];
    const float* ln_b   = (const float*)d_in[4];
    const float* Win    = (const float*)d_in[5];
    const float* convw  = (const float*)d_in[6];
    const float* convb  = (const float*)d_in[7];
    const float* dt_bias= (const float*)d_in[8];
    const float* A_log  = (const float*)d_in[9];
    const float* Dp     = (const float*)d_in[10];
    const float* normw  = (const float*)d_in[11];
    const float* Wout   = (const float*)d_in[12];
    const float* fn_w   = (const float*)d_in[13];
    const float* fn_b   = (const float*)d_in[14];
    const float* Wpo    = (const float*)d_in[15];
    const float* bpo    = (const float*)d_in[16];
    float* out = (float*)d_out;

    float *ph, *phn, *pzx, *py, *phf;
    cudaGetSymbolAddress((void**)&ph,  g_h);
    cudaGetSymbolAddress((void**)&phn, g_hn);
    cudaGetSymbolAddress((void**)&pzx, g_zx);
    cudaGetSymbolAddress((void**)&py,  g_y);
    cudaGetSymbolAddress((void**)&phf, g_hfin);

    // h = x @ Wpi + bpi   (M=2048, N=512, K=80)
    gemm_k<false, true><<<dim3(8, 16, 1), 256>>>(x, Wpi, bpi, ph, NTOK, DMODEL, FEAT, 0, 0);

    for (int l = 0; l < 2; l++) {
        // hn = LN(h)
        layernorm_k<<<NTOK, 256>>>(ph, ln_w + l * DMODEL, ln_b + l * DMODEL, phn);
        // zxbcdt[dir] = hn @ Win[l,dir]   (both dirs in one launch, z=2)
        gemm_k<false, false><<<dim3(33, 16, 2), 256>>>(
            phn, Win + (long)l * 2 * DMODEL * DINPROJ, nullptr, pzx,
            NTOK, DINPROJ, DMODEL, (long)DMODEL * DINPROJ, (long)NTOK * DINPROJ);
        // depthwise conv + silu (both dirs)
        conv_silu_k<<<dim3(9, SEQ, 4), 128>>>(convw, convb, l);
        // dt/dA precompute
        dtprep_k<<<(2 * NTOK * NHEADS + 255) / 256, 256>>>(dt_bias, A_log, l);
        // selective scan + D skip + silu(z) gate
        scan_k<<<64, 64>>>(Dp, l);
        // RMS norm * normw (in-place)
        rmsnorm_k<<<2 * NTOK, 256>>>(normw, l);
        // h += y[dir] @ Wout[l,dir]  (residual already in h)
        for (int dir = 0; dir < 2; dir++)
            gemm_k<true, false><<<dim3(8, 16, 1), 256>>>(
                py + (long)dir * NTOK * DINNER,
                Wout + (long)(l * 2 + dir) * DINNER * DMODEL,
                nullptr, ph, NTOK, DMODEL, DINNER, 0, 0);
    }

    // final LN, pred = hfin @ Wpo + bpo, output (pred, hfin)
    layernorm_k<<<NTOK, 256>>>(ph, fn_w, fn_b, phf);
    gemm_k<false, true><<<dim3(2, 16, 1), 256>>>(phf, Wpo, bpo, out, NTOK, FEAT, DMODEL, 0, 0);
    copy_hfin_k<<<(NTOK * DMODEL + 255) / 256, 256>>>(out + NTOK * FEAT);
}

// round 3
// speedup vs baseline: 1.2828x; 1.2828x over previous
#include <cuda_runtime.h>
#include <cuda_bf16.h>
#include <math.h>

#define BATCH 2
#define SEQ 1024
#define FEAT 80
#define DMODEL 512
#define DSTATE 16
#define DCONV 7
#define HEADDIM 64
#define DINNER 1024
#define NHEADS 16
#define CONVDIM 1056
#define DINPROJ 2096
#define NTOK (BATCH*SEQ)
#define EPSF 1e-5f

// ---------------- scratch (device globals: allocation-free) ----------------
__device__ float g_h[NTOK*DMODEL];
__device__ float g_hn[NTOK*DMODEL];
__device__ float g_zx[2][NTOK*DINPROJ];
__device__ float g_xbc[2][NTOK*CONVDIM];
__device__ float g_dt[2][NTOK*NHEADS];
__device__ float g_dA[2][NTOK*NHEADS];
__device__ float g_y[2][NTOK*DINNER];
__device__ float g_hfin[NTOK*DMODEL];

// ---------------- helpers ----------------
__device__ __forceinline__ void cvt_hl(float v, __nv_bfloat16& h, __nv_bfloat16& l) {
    h = __float2bfloat16_rn(v);
    l = __float2bfloat16_rn(v - __bfloat162float(h));
}

__device__ __forceinline__ void ldsm_x4(unsigned r[4], unsigned addr) {
    asm volatile("ldmatrix.sync.aligned.m8n8.x4.shared.b16 {%0,%1,%2,%3}, [%4];"
        : "=r"(r[0]), "=r"(r[1]), "=r"(r[2]), "=r"(r[3]) : "r"(addr));
}
__device__ __forceinline__ void ldsm_x2t(unsigned r[2], unsigned addr) {
    asm volatile("ldmatrix.sync.aligned.m8n8.x2.trans.shared.b16 {%0,%1}, [%2];"
        : "=r"(r[0]), "=r"(r[1]) : "r"(addr));
}
__device__ __forceinline__ void mma16816(float d[4], const unsigned a[4], const unsigned b[2]) {
    asm volatile("mma.sync.aligned.m16n8k16.row.col.f32.bf16.bf16.f32 "
        "{%0,%1,%2,%3}, {%4,%5,%6,%7}, {%8,%9}, {%0,%1,%2,%3};"
        : "+f"(d[0]), "+f"(d[1]), "+f"(d[2]), "+f"(d[3])
        : "r"(a[0]), "r"(a[1]), "r"(a[2]), "r"(a[3]), "r"(b[0]), "r"(b[1]));
}

// ---------------- tensor-core GEMM: C[M,N] (+)= A[M,K] @ B[K,N] (+bias) ----
// BM=128, BN=64, BK=32, 256 threads (8 warps, 4x2 warp grid, 32x32 warp tile).
// fp32 in/out; internally bf16 hi/lo 3-pass (A_h*B_h + A_l*B_h + A_h*B_l).
// M must be a multiple of 128. K, N arbitrary (zero-fill / store guards).
template<bool ACCUM, bool BIAS>
__global__ void __launch_bounds__(256) gemm_tc(
    const float* __restrict__ A, const float* __restrict__ B,
    const float* __restrict__ bias, float* __restrict__ C,
    int M, int N, int K, long bz, long cz)
{
    B += (long)blockIdx.z * bz;
    C += (long)blockIdx.z * cz;
    const int m0 = blockIdx.y * 128;
    const int n0 = blockIdx.x * 64;

    __shared__ __nv_bfloat16 Ah[128][40], Al[128][40];
    __shared__ __nv_bfloat16 Bh[32][72], Bl[32][72];

    const int tid = threadIdx.x;
    const int warp = tid >> 5, lane = tid & 31;
    const int wm = (warp & 3) * 32;      // warp row offset in tile
    const int wn = (warp >> 2) * 32;     // warp col offset in tile

    float acc[2][4][4];
    #pragma unroll
    for (int f = 0; f < 2; f++)
        #pragma unroll
        for (int g = 0; g < 4; g++)
            #pragma unroll
            for (int i = 0; i < 4; i++) acc[f][g][i] = 0.f;

    const int arow = tid >> 3, aq = (tid & 7) * 4;    // A: 4 rows strided 32
    const int brow = tid >> 4, bq = (tid & 15) * 4;   // B: 2 rows strided 16

    for (int k0 = 0; k0 < K; k0 += 32) {
        // ---- stage A tile (128x32) with hi/lo conversion ----
        #pragma unroll
        for (int i = 0; i < 4; i++) {
            int r = arow + i * 32;
            const float* src = A + (long)(m0 + r) * K + k0 + aq;
            float4 v;
            if (k0 + aq + 3 < K) v = *(const float4*)src;
            else {
                v.x = (k0 + aq + 0 < K) ? src[0] : 0.f;
                v.y = (k0 + aq + 1 < K) ? src[1] : 0.f;
                v.z = (k0 + aq + 2 < K) ? src[2] : 0.f;
                v.w = (k0 + aq + 3 < K) ? src[3] : 0.f;
            }
            __nv_bfloat16 h0, l0, h1, l1, h2, l2, h3, l3;
            cvt_hl(v.x, h0, l0); cvt_hl(v.y, h1, l1);
            cvt_hl(v.z, h2, l2); cvt_hl(v.w, h3, l3);
            *(__nv_bfloat162*)&Ah[r][aq]     = __nv_bfloat162(h0, h1);
            *(__nv_bfloat162*)&Ah[r][aq + 2] = __nv_bfloat162(h2, h3);
            *(__nv_bfloat162*)&Al[r][aq]     = __nv_bfloat162(l0, l1);
            *(__nv_bfloat162*)&Al[r][aq + 2] = __nv_bfloat162(l2, l3);
        }
        // ---- stage B tile (32x64) ----
        #pragma unroll
        for (int i = 0; i < 2; i++) {
            int r = brow + i * 16;
            const float* src = B + (long)(k0 + r) * N + n0 + bq;
            float4 v;
            bool kok = (k0 + r < K);
            if (kok && n0 + bq + 3 < N) v = *(const float4*)src;
            else {
                v.x = (kok && n0 + bq + 0 < N) ? src[0] : 0.f;
                v.y = (kok && n0 + bq + 1 < N) ? src[1] : 0.f;
                v.z = (kok && n0 + bq + 2 < N) ? src[2] : 0.f;
                v.w = (kok && n0 + bq + 3 < N) ? src[3] : 0.f;
            }
            __nv_bfloat16 h0, l0, h1, l1, h2, l2, h3, l3;
            cvt_hl(v.x, h0, l0); cvt_hl(v.y, h1, l1);
            cvt_hl(v.z, h2, l2); cvt_hl(v.w, h3, l3);
            *(__nv_bfloat162*)&Bh[r][bq]     = __nv_bfloat162(h0, h1);
            *(__nv_bfloat162*)&Bh[r][bq + 2] = __nv_bfloat162(h2, h3);
            *(__nv_bfloat162*)&Bl[r][bq]     = __nv_bfloat162(l0, l1);
            *(__nv_bfloat162*)&Bl[r][bq + 2] = __nv_bfloat162(l2, l3);
        }
        __syncthreads();

        // ---- compute: 2 k16 steps ----
        #pragma unroll
        for (int ks = 0; ks < 2; ks++) {
            const int kk = ks * 16;
            unsigned ah[2][4], al[2][4], bh[4][2], bl[4][2];
            #pragma unroll
            for (int f = 0; f < 2; f++) {
                int row = wm + f * 16 + (lane & 15);
                int col = kk + ((lane >> 4) << 3);
                ldsm_x4(ah[f], (unsigned)__cvta_generic_to_shared(&Ah[row][col]));
                ldsm_x4(al[f], (unsigned)__cvta_generic_to_shared(&Al[row][col]));
            }
            #pragma unroll
            for (int g = 0; g < 4; g++) {
                int row = kk + (lane & 15);
                int col = wn + g * 8;
                ldsm_x2t(bh[g], (unsigned)__cvta_generic_to_shared(&Bh[row][col]));
                ldsm_x2t(bl[g], (unsigned)__cvta_generic_to_shared(&Bl[row][col]));
            }
            #pragma unroll
            for (int f = 0; f < 2; f++)
                #pragma unroll
                for (int g = 0; g < 4; g++) {
                    mma16816(acc[f][g], ah[f], bh[g]);
                    mma16816(acc[f][g], al[f], bh[g]);
                    mma16816(acc[f][g], ah[f], bl[g]);
                }
        }
        __syncthreads();
    }

    // ---- epilogue ----
    const int cr = lane >> 2, cc = (lane & 3) * 2;
    #pragma unroll
    for (int f = 0; f < 2; f++) {
        #pragma unroll
        for (int g = 0; g < 4; g++) {
            int mm = m0 + wm + f * 16 + cr;
            int nn = n0 + wn + g * 8 + cc;
            #pragma unroll
            for (int half = 0; half < 2; half++) {
                int m = mm + half * 8;
                float v0 = acc[f][g][half * 2], v1 = acc[f][g][half * 2 + 1];
                if (nn < N) {
                    long idx = (long)m * N + nn;
                    float v = v0;
                    if (BIAS) v += bias[nn];
                    if (ACCUM) v += C[idx];
                    C[idx] = v;
                }
                if (nn + 1 < N) {
                    long idx = (long)m * N + nn + 1;
                    float v = v1;
                    if (BIAS) v += bias[nn + 1];
                    if (ACCUM) v += C[idx];
                    C[idx] = v;
                }
            }
        }
    }
}

// ---------------- reductions ----------------
__device__ __forceinline__ float warpSum(float v) {
    #pragma unroll
    for (int o = 16; o; o >>= 1) v += __shfl_down_sync(0xffffffffu, v, o);
    return v;
}

// ---------------- layernorm over DMODEL=512, 256 threads/row ----------------
__global__ void __launch_bounds__(256) layernorm_k(
    const float* __restrict__ in, const float* __restrict__ w,
    const float* __restrict__ b, float* __restrict__ out)
{
    __shared__ float sbuf[8];
    int row = blockIdx.x;
    int tid = threadIdx.x;
    const float* v = in + (long)row * DMODEL;
    float x0 = v[tid], x1 = v[tid + 256];
    float s = warpSum(x0 + x1);
    if ((tid & 31) == 0) sbuf[tid >> 5] = s;
    __syncthreads();
    float mean = 0.f;
    #pragma unroll
    for (int i = 0; i < 8; i++) mean += sbuf[i];
    mean *= (1.f / DMODEL);
    __syncthreads();
    float c0 = x0 - mean, c1 = x1 - mean;
    float ss = warpSum(c0 * c0 + c1 * c1);
    if ((tid & 31) == 0) sbuf[tid >> 5] = ss;
    __syncthreads();
    float var = 0.f;
    #pragma unroll
    for (int i = 0; i < 8; i++) var += sbuf[i];
    var *= (1.f / DMODEL);
    float rs = rsqrtf(var + EPSF);
    out[(long)row * DMODEL + tid]       = c0 * rs * w[tid] + b[tid];
    out[(long)row * DMODEL + tid + 256] = c1 * rs * w[tid + 256] + b[tid + 256];
}

// ---------------- causal depthwise conv (direction-aware) + SiLU -----------
__global__ void __launch_bounds__(128) conv_silu_k(
    const float* __restrict__ convw, const float* __restrict__ convb, int l)
{
    int c = blockIdx.x * 128 + threadIdx.x;
    if (c >= CONVDIM) return;
    int tau = blockIdx.y;
    int dir = blockIdx.z >> 1;
    int b = blockIdx.z & 1;
    const float* w = convw + ((long)((l * 2 + dir) * CONVDIM) + c) * DCONV;
    float acc = convb[(l * 2 + dir) * CONVDIM + c];
    const float* zxp = g_zx[dir];
    #pragma unroll
    for (int k = 0; k < DCONV; k++) {
        int ts = tau - (DCONV - 1) + k;
        if (ts >= 0) {
            int o = dir ? (SEQ - 1 - ts) : ts;
            acc += w[k] * zxp[(long)(b * SEQ + o) * DINPROJ + DINNER + c];
        }
    }
    float s = acc / (1.f + expf(-acc));
    int oo = dir ? (SEQ - 1 - tau) : tau;
    g_xbc[dir][(long)(b * SEQ + oo) * CONVDIM + c] = s;
}

// ---------------- precompute dt (softplus) and dA=exp(dt*A), fully parallel -
__global__ void __launch_bounds__(256) dtprep_k(
    const float* __restrict__ dt_bias, const float* __restrict__ A_log, int l)
{
    int idx = blockIdx.x * 256 + threadIdx.x;
    if (idx >= 2 * NTOK * NHEADS) return;
    int dir = idx / (NTOK * NHEADS);
    int r = idx - dir * (NTOK * NHEADS);
    int h = r & 15;
    int tok = r >> 4;
    float raw = g_zx[dir][(long)tok * DINPROJ + DINNER + CONVDIM + h];
    float xv = raw + dt_bias[(l * 2 + dir) * NHEADS + h];
    float dt = (xv > 20.f) ? xv : log1pf(expf(xv));
    float Av = -expf(A_log[(l * 2 + dir) * NHEADS + h]);
    g_dt[dir][r] = dt;
    g_dA[dir][r] = expf(dt * Av);
}

// ---------------- selective-state scan, chunked 8 steps per barrier --------
__global__ void __launch_bounds__(64) scan_k(const float* __restrict__ Dp, int l)
{
    int bid = blockIdx.x;
    int dir = bid >> 5;
    int b = (bid >> 4) & 1;
    int h = bid & 15;
    int p = threadIdx.x;
    const float* xbc = g_xbc[dir];
    const float* zx = g_zx[dir];
    const float* dtp = g_dt[dir];
    const float* dAp = g_dA[dir];
    float* yo = g_y[dir];
    const float Dv = Dp[(l * 2 + dir) * NHEADS + h];
    float hs[16];
    #pragma unroll
    for (int n = 0; n < 16; n++) hs[n] = 0.f;
    __shared__ float sB[8][16], sC[8][16], sdt[8], sdA[8];

    for (int t0 = 0; t0 < SEQ; t0 += 8) {
        #pragma unroll
        for (int i = p; i < 128; i += 64) {
            int tt = i >> 4, n = i & 15;
            int o = dir ? (SEQ - 1 - (t0 + tt)) : (t0 + tt);
            long base = (long)(b * SEQ + o) * CONVDIM + DINNER;
            sB[tt][n] = xbc[base + n];
            sC[tt][n] = xbc[base + DSTATE + n];
        }
        if (p < 8) {
            int o = dir ? (SEQ - 1 - (t0 + p)) : (t0 + p);
            sdt[p] = dtp[(long)(b * SEQ + o) * NHEADS + h];
            sdA[p] = dAp[(long)(b * SEQ + o) * NHEADS + h];
        }
        __syncthreads();

        float xt[8], zt[8];
        int oidx[8];
        #pragma unroll
        for (int j = 0; j < 8; j++) {
            int o = dir ? (SEQ - 1 - (t0 + j)) : (t0 + j);
            oidx[j] = o;
            xt[j] = xbc[(long)(b * SEQ + o) * CONVDIM + h * HEADDIM + p];
            zt[j] = zx[(long)(b * SEQ + o) * DINPROJ + h * HEADDIM + p];
        }
        #pragma unroll
        for (int j = 0; j < 8; j++) {
            float dt = sdt[j], dA = sdA[j];
            float cdt = dt * xt[j];
            float y = 0.f;
            #pragma unroll
            for (int n = 0; n < 16; n++) {
                hs[n] = hs[n] * dA + cdt * sB[j][n];
                y += hs[n] * sC[j][n];
            }
            y += Dv * xt[j];
            float z = zt[j];
            float sil = z / (1.f + expf(-z));
            yo[(long)(b * SEQ + oidx[j]) * DINNER + h * HEADDIM + p] = y * sil;
        }
        __syncthreads();
    }
}

// ---------------- RMS norm over DINNER=1024 (in-place on g_y) --------------
__global__ void __launch_bounds__(256) rmsnorm_k(const float* __restrict__ normw, int l)
{
    __shared__ float sbuf[8];
    int bid = blockIdx.x;
    int dir = bid >> 11;
    int tok = bid & (NTOK - 1);
    int tid = threadIdx.x;
    float* v = g_y[dir] + (long)tok * DINNER;
    const float* w = normw + (l * 2 + dir) * DINNER;
    float vals[4];
    float ss = 0.f;
    #pragma unroll
    for (int i = 0; i < 4; i++) {
        vals[i] = v[tid + i * 256];
        ss += vals[i] * vals[i];
    }
    ss = warpSum(ss);
    if ((tid & 31) == 0) sbuf[tid >> 5] = ss;
    __syncthreads();
    float tot = 0.f;
    #pragma unroll
    for (int i = 0; i < 8; i++) tot += sbuf[i];
    float rs = rsqrtf(tot * (1.f / DINNER) + EPSF);
    #pragma unroll
    for (int i = 0; i < 4; i++)
        v[tid + i * 256] = vals[i] * rs * w[tid + i * 256];
}

// ---------------- copy final h into d_out tail ----------------
__global__ void __launch_bounds__(256) copy_hfin_k(float* __restrict__ out)
{
    int i = blockIdx.x * 256 + threadIdx.x;
    if (i < NTOK * DMODEL) out[i] = g_hfin[i];
}

// ---------------- launch ----------------
extern "C" void kernel_launch(void* const* d_in, const int* in_sizes, int n_in,
                              void* d_out, int out_size)
{
    const float* x      = (const float*)d_in[0];
    const float* Wpi    = (const float*)d_in[1];
    const float* bpi    = (const float*)d_in[2];
    const float* ln_w   = (const float*)d_in[3];
    const float* ln_b   = (const float*)d_in[4];
    const float* Win    = (const float*)d_in[5];
    const float* convw  = (const float*)d_in[6];
    const float* convb  = (const float*)d_in[7];
    const float* dt_bias= (const float*)d_in[8];
    const float* A_log  = (const float*)d_in[9];
    const float* Dp     = (const float*)d_in[10];
    const float* normw  = (const float*)d_in[11];
    const float* Wout   = (const float*)d_in[12];
    const float* fn_w   = (const float*)d_in[13];
    const float* fn_b   = (const float*)d_in[14];
    const float* Wpo    = (const float*)d_in[15];
    const float* bpo    = (const float*)d_in[16];
    float* out = (float*)d_out;

    float *ph, *phn, *pzx, *py, *phf;
    cudaGetSymbolAddress((void**)&ph,  g_h);
    cudaGetSymbolAddress((void**)&phn, g_hn);
    cudaGetSymbolAddress((void**)&pzx, g_zx);
    cudaGetSymbolAddress((void**)&py,  g_y);
    cudaGetSymbolAddress((void**)&phf, g_hfin);

    // h = x @ Wpi + bpi   (M=2048, N=512, K=80)
    gemm_tc<false, true><<<dim3(8, 16, 1), 256>>>(x, Wpi, bpi, ph, NTOK, DMODEL, FEAT, 0, 0);

    for (int l = 0; l < 2; l++) {
        layernorm_k<<<NTOK, 256>>>(ph, ln_w + l * DMODEL, ln_b + l * DMODEL, phn);
        // zxbcdt[dir] = hn @ Win[l,dir]   (both dirs, z=2)
        gemm_tc<false, false><<<dim3(33, 16, 2), 256>>>(
            phn, Win + (long)l * 2 * DMODEL * DINPROJ, nullptr, pzx,
            NTOK, DINPROJ, DMODEL, (long)DMODEL * DINPROJ, (long)NTOK * DINPROJ);
        conv_silu_k<<<dim3(9, SEQ, 4), 128>>>(convw, convb, l);
        dtprep_k<<<(2 * NTOK * NHEADS + 255) / 256, 256>>>(dt_bias, A_log, l);
        scan_k<<<64, 64>>>(Dp, l);
        rmsnorm_k<<<2 * NTOK, 256>>>(normw, l);
        // h += y[dir] @ Wout[l,dir]
        for (int dir = 0; dir < 2; dir++)
            gemm_tc<true, false><<<dim3(8, 16, 1), 256>>>(
                py + (long)dir * NTOK * DINNER,
                Wout + (long)(l * 2 + dir) * DINNER * DMODEL,
                nullptr, ph, NTOK, DMODEL, DINNER, 0, 0);
    }

    layernorm_k<<<NTOK, 256>>>(ph, fn_w, fn_b, phf);
    gemm_tc<false, true><<<dim3(2, 16, 1), 256>>>(phf, Wpo, bpo, out, NTOK, FEAT, DMODEL, 0, 0);
    copy_hfin_k<<<(NTOK * DMODEL + 255) / 256, 256>>>(out + NTOK * FEAT);
}

// round 5
// speedup vs baseline: 2.8298x; 2.2059x over previous
#include <cuda_runtime.h>
#include <cuda_bf16.h>
#include <math.h>
#include <stdint.h>

#define BATCH 2
#define SEQ 1024
#define FEAT 80
#define DMODEL 512
#define DSTATE 16
#define DCONV 7
#define HEADDIM 64
#define DINNER 1024
#define NHEADS 16
#define CONVDIM 1056
#define DINPROJ 2096
#define NTOK (BATCH*SEQ)
#define EPSF 1e-5f
#define KPI 128          // padded K for input projection (FEAT=80 -> 128)
#define CH 16            // scan chunks
#define CL 64            // steps per chunk

// ---------------- scratch (device globals: allocation-free) ----------------
__device__ float g_h[NTOK*DMODEL];
__device__ float g_zx[2][NTOK*DINPROJ];
__device__ float g_xbc[2][NTOK*CONVDIM];
__device__ float g_dt[2][NTOK*NHEADS];
__device__ float g_dA[2][NTOK*NHEADS];
__device__ float g_y[2][NTOK*DINNER];
__device__ float g_hfin[NTOK*DMODEL];
__device__ float g_ytmp[2][NTOK*DMODEL];

// scan chunk state
__device__ float g_S[2*2*16*CH*64*16];
__device__ float g_Hc[2*2*16*CH*64*16];
__device__ float g_cA[2][NTOK*NHEADS];

// bf16 hi/lo activations
__device__ __nv_bfloat16 g_hnh[NTOK*DMODEL],  g_hnl[NTOK*DMODEL];
__device__ __nv_bfloat16 g_xh[NTOK*KPI],      g_xl[NTOK*KPI];
__device__ __nv_bfloat16 g_yh[2][NTOK*DINNER],g_yl[2][NTOK*DINNER];
__device__ __nv_bfloat16 g_hfh[NTOK*DMODEL],  g_hfl[NTOK*DMODEL];

// bf16 hi/lo weights in original [K][N] layout (K zero-padded)
__device__ __nv_bfloat16 g_winh[4L*DMODEL*DINPROJ], g_winl[4L*DMODEL*DINPROJ];
__device__ __nv_bfloat16 g_wouth[4L*DINNER*DMODEL], g_woutl[4L*DINNER*DMODEL];
__device__ __nv_bfloat16 g_wpih[KPI*DMODEL],        g_wpil[KPI*DMODEL];
__device__ __nv_bfloat16 g_wpoh[DMODEL*FEAT],       g_wpol[DMODEL*FEAT];

// ---------------- helpers ----------------
__device__ __forceinline__ void cvt_hl(float v, __nv_bfloat16& h, __nv_bfloat16& l) {
    h = __float2bfloat16_rn(v);
    l = __float2bfloat16_rn(v - __bfloat162float(h));
}
__device__ __forceinline__ uint32_t smem_u32(const void* p) {
    uint32_t a;
    asm("{ .reg .u64 t; cvta.to.shared.u64 t, %1; cvt.u32.u64 %0, t; }" : "=r"(a) : "l"(p));
    return a;
}
__device__ __forceinline__ void cpa16(uint32_t dst, const void* src) {
    asm volatile("cp.async.cg.shared.global [%0], [%1], 16;" :: "r"(dst), "l"(src));
}
__device__ __forceinline__ void ldsm_x4(unsigned r[4], uint32_t addr) {
    asm volatile("ldmatrix.sync.aligned.m8n8.x4.shared.b16 {%0,%1,%2,%3}, [%4];"
        : "=r"(r[0]), "=r"(r[1]), "=r"(r[2]), "=r"(r[3]) : "r"(addr));
}
__device__ __forceinline__ void ldsm_x2t(unsigned r[2], uint32_t addr) {
    asm volatile("ldmatrix.sync.aligned.m8n8.x2.trans.shared.b16 {%0,%1}, [%2];"
        : "=r"(r[0]), "=r"(r[1]) : "r"(addr));
}
__device__ __forceinline__ void mma16816(float d[4], const unsigned a[4], const unsigned b[2]) {
    asm volatile("mma.sync.aligned.m16n8k16.row.col.f32.bf16.bf16.f32 "
        "{%0,%1,%2,%3}, {%4,%5,%6,%7}, {%8,%9}, {%0,%1,%2,%3};"
        : "+f"(d[0]), "+f"(d[1]), "+f"(d[2]), "+f"(d[3])
        : "r"(a[0]), "r"(a[1]), "r"(a[2]), "r"(a[3]), "r"(b[0]), "r"(b[1]));
}

// ---------------- GEMM: C[M,N](+)= A[M,K]@B[K,N] (+bias), bf16 hi/lo 3-pass -
// BM=128, BN=128, BK=32, 256 thr, 8 warps (2M x 4N), warp tile 64x32.
// A,B pre-split bf16 hi/lo in gmem. M mult 128, K mult 32, N mult 8.
#define ASTR 80    // bytes per A smem row (40 halves)
#define BSTR 272   // bytes per B smem row (136 halves)
#define OFF_AL 10240
#define OFF_BH 20480
#define OFF_BL 29184
#define STAGE 37888
#define GSMEM (2*STAGE)

__device__ __forceinline__ void g5_stage(
    uint32_t sb, const __nv_bfloat16* Ah, const __nv_bfloat16* Al,
    const __nv_bfloat16* Bh, const __nv_bfloat16* Bl,
    int m0, int n0, int k0, int N, int K, int tid)
{
    #pragma unroll
    for (int q = 0; q < 2; q++) {
        int idx = q * 256 + tid, row = idx >> 2, seg = idx & 3;
        uint32_t d = sb + row * ASTR + seg * 16;
        const __nv_bfloat16* s = Ah + (size_t)(m0 + row) * K + k0 + seg * 8;
        cpa16(d, s);
        cpa16(d + OFF_AL, Al + (s - Ah));
    }
    #pragma unroll
    for (int q = 0; q < 2; q++) {
        int idx = q * 256 + tid, row = idx >> 4, seg = idx & 15;
        uint32_t d = sb + OFF_BH + row * BSTR + seg * 16;
        if (n0 + seg * 8 < N) {
            const __nv_bfloat16* s = Bh + (size_t)(k0 + row) * N + n0 + seg * 8;
            cpa16(d, s);
            cpa16(d + 8704, Bl + (s - Bh));
        } else {
            asm volatile("st.shared.v4.b32 [%0], {%1,%1,%1,%1};" :: "r"(d), "r"(0) : "memory");
            asm volatile("st.shared.v4.b32 [%0], {%1,%1,%1,%1};" :: "r"(d + 8704), "r"(0) : "memory");
        }
    }
    asm volatile("cp.async.commit_group;" ::: "memory");
}

template<bool ACCUM, bool BIAS>
__global__ void __launch_bounds__(256) gemm5(
    const __nv_bfloat16* __restrict__ Ah, const __nv_bfloat16* __restrict__ Al,
    const __nv_bfloat16* __restrict__ Bh, const __nv_bfloat16* __restrict__ Bl,
    const float* __restrict__ bias, float* __restrict__ C,
    int N, int K, long az, long bz, long cz)
{
    extern __shared__ char dsm[];
    Ah += (long)blockIdx.z * az;  Al += (long)blockIdx.z * az;
    Bh += (long)blockIdx.z * bz;  Bl += (long)blockIdx.z * bz;
    C  += (long)blockIdx.z * cz;
    const int m0 = blockIdx.y * 128, n0 = blockIdx.x * 128;
    const int tid = threadIdx.x, warp = tid >> 5, lane = tid & 31;
    const int wm = (warp & 1) * 64, wn = (warp >> 1) * 32;
    const uint32_t raw = smem_u32(dsm);

    float acc[4][4][4];
    #pragma unroll
    for (int f = 0; f < 4; f++)
        #pragma unroll
        for (int g = 0; g < 4; g++)
            #pragma unroll
            for (int i = 0; i < 4; i++) acc[f][g][i] = 0.f;

    const int nch = K >> 5;
    g5_stage(raw, Ah, Al, Bh, Bl, m0, n0, 0, N, K, tid);

    for (int c = 0; c < nch; c++) {
        if (c + 1 < nch) {
            g5_stage(raw + (uint32_t)((c + 1) & 1) * STAGE,
                     Ah, Al, Bh, Bl, m0, n0, (c + 1) << 5, N, K, tid);
            asm volatile("cp.async.wait_group 1;" ::: "memory");
        } else {
            asm volatile("cp.async.wait_group 0;" ::: "memory");
        }
        __syncthreads();

        const uint32_t sb = raw + (uint32_t)(c & 1) * STAGE;
        #pragma unroll
        for (int ks = 0; ks < 2; ks++) {
            const int kk = ks * 16;
            unsigned ah[4][4], al[4][4], bh[4][2], bl[4][2];
            #pragma unroll
            for (int f = 0; f < 4; f++) {
                int row = wm + f * 16 + (lane & 15);
                int col = kk + ((lane >> 4) << 3);
                uint32_t a = sb + row * ASTR + col * 2;
                ldsm_x4(ah[f], a);
                ldsm_x4(al[f], a + OFF_AL);
            }
            #pragma unroll
            for (int g = 0; g < 4; g++) {
                int row = kk + (lane & 15);
                int col = wn + g * 8;
                uint32_t a = sb + OFF_BH + row * BSTR + col * 2;
                ldsm_x2t(bh[g], a);
                ldsm_x2t(bl[g], a + 8704);
            }
            #pragma unroll
            for (int f = 0; f < 4; f++)
                #pragma unroll
                for (int g = 0; g < 4; g++) {
                    mma16816(acc[f][g], ah[f], bh[g]);
                    mma16816(acc[f][g], al[f], bh[g]);
                    mma16816(acc[f][g], ah[f], bl[g]);
                }
        }
        __syncthreads();
    }

    const int cr = lane >> 2, cc = (lane & 3) * 2;
    #pragma unroll
    for (int f = 0; f < 4; f++) {
        #pragma unroll
        for (int g = 0; g < 4; g++) {
            int mmb = m0 + wm + f * 16 + cr;
            int nn = n0 + wn + g * 8 + cc;
            #pragma unroll
            for (int half = 0; half < 2; half++) {
                int m = mmb + half * 8;
                #pragma unroll
                for (int j = 0; j < 2; j++) {
                    if (nn + j < N) {
                        float v = acc[f][g][half * 2 + j];
                        long o = (long)m * N + nn + j;
                        if (BIAS) v += bias[nn + j];
                        if (ACCUM) v += C[o];
                        C[o] = v;
                    }
                }
            }
        }
    }
}

// ---------------- weight convert (no transpose): W[K][N] -> bf16 hi/lo, K padded
__global__ void __launch_bounds__(256) cvt_w_k(
    const float* __restrict__ W, __nv_bfloat16* __restrict__ Wh,
    __nv_bfloat16* __restrict__ Wl, int K, int N, int Kpad, long wz, long oz)
{
    long idx = (long)blockIdx.x * 256 + threadIdx.x;
    if (idx >= (long)Kpad * N) return;
    W  += (long)blockIdx.z * wz;
    Wh += (long)blockIdx.z * oz;
    Wl += (long)blockIdx.z * oz;
    int k = (int)(idx / N);
    int n = (int)(idx - (long)k * N);
    float v = (k < K) ? W[(long)k * N + n] : 0.f;
    __nv_bfloat16 h, l;
    cvt_hl(v, h, l);
    Wh[idx] = h; Wl[idx] = l;
}

// ---------------- x -> bf16 hi/lo, K padded 80->128 ----------------
__global__ void __launch_bounds__(256) cvt_x_k(const float* __restrict__ x)
{
    int idx = blockIdx.x * 256 + threadIdx.x;
    if (idx >= NTOK * KPI) return;
    int mrow = idx >> 7, c = idx & (KPI - 1);
    float v = (c < FEAT) ? x[mrow * FEAT + c] : 0.f;
    __nv_bfloat16 h, l;
    cvt_hl(v, h, l);
    g_xh[idx] = h; g_xl[idx] = l;
}

// ---------------- reductions ----------------
__device__ __forceinline__ float warpSum(float v) {
    #pragma unroll
    for (int o = 16; o; o >>= 1) v += __shfl_down_sync(0xffffffffu, v, o);
    return v;
}

// ---------------- layernorm (512) -> bf16 hi/lo (+opt fp32) ----------------
__global__ void __launch_bounds__(256) layernorm_hl_k(
    const float* __restrict__ in, const float* __restrict__ w,
    const float* __restrict__ b, __nv_bfloat16* __restrict__ oh,
    __nv_bfloat16* __restrict__ ol, float* __restrict__ of)
{
    __shared__ float sbuf[8];
    int row = blockIdx.x, tid = threadIdx.x;
    const float* v = in + (long)row * DMODEL;
    float x0 = v[tid], x1 = v[tid + 256];
    float s = warpSum(x0 + x1);
    if ((tid & 31) == 0) sbuf[tid >> 5] = s;
    __syncthreads();
    float mean = 0.f;
    #pragma unroll
    for (int i = 0; i < 8; i++) mean += sbuf[i];
    mean *= (1.f / DMODEL);
    __syncthreads();
    float c0 = x0 - mean, c1 = x1 - mean;
    float ss = warpSum(c0 * c0 + c1 * c1);
    if ((tid & 31) == 0) sbuf[tid >> 5] = ss;
    __syncthreads();
    float var = 0.f;
    #pragma unroll
    for (int i = 0; i < 8; i++) var += sbuf[i];
    var *= (1.f / DMODEL);
    float rs = rsqrtf(var + EPSF);
    float r0 = c0 * rs * w[tid] + b[tid];
    float r1 = c1 * rs * w[tid + 256] + b[tid + 256];
    __nv_bfloat16 h, l;
    long o0 = (long)row * DMODEL + tid, o1 = o0 + 256;
    cvt_hl(r0, h, l); oh[o0] = h; ol[o0] = l;
    cvt_hl(r1, h, l); oh[o1] = h; ol[o1] = l;
    if (of) { of[o0] = r0; of[o1] = r1; }
}

// ---------------- causal depthwise conv + SiLU ----------------
__global__ void __launch_bounds__(128) conv_silu_k(
    const float* __restrict__ convw, const float* __restrict__ convb, int l)
{
    int c = blockIdx.x * 128 + threadIdx.x;
    if (c >= CONVDIM) return;
    int tau = blockIdx.y;
    int dir = blockIdx.z >> 1;
    int b = blockIdx.z & 1;
    const float* w = convw + ((long)((l * 2 + dir) * CONVDIM) + c) * DCONV;
    float acc = convb[(l * 2 + dir) * CONVDIM + c];
    const float* zxp = g_zx[dir];
    #pragma unroll
    for (int k = 0; k < DCONV; k++) {
        int ts = tau - (DCONV - 1) + k;
        if (ts >= 0) {
            int o = dir ? (SEQ - 1 - ts) : ts;
            acc += w[k] * zxp[(long)(b * SEQ + o) * DINPROJ + DINNER + c];
        }
    }
    float s = acc / (1.f + expf(-acc));
    int oo = dir ? (SEQ - 1 - tau) : tau;
    g_xbc[dir][(long)(b * SEQ + oo) * CONVDIM + c] = s;
}

// ---------------- dt/dA precompute ----------------
__global__ void __launch_bounds__(256) dtprep_k(
    const float* __restrict__ dt_bias, const float* __restrict__ A_log, int l)
{
    int idx = blockIdx.x * 256 + threadIdx.x;
    if (idx >= 2 * NTOK * NHEADS) return;
    int dir = idx / (NTOK * NHEADS);
    int r = idx - dir * (NTOK * NHEADS);
    int h = r & 15;
    int tok = r >> 4;
    float raw = g_zx[dir][(long)tok * DINPROJ + DINNER + CONVDIM + h];
    float xv = raw + dt_bias[(l * 2 + dir) * NHEADS + h];
    float dt = (xv > 20.f) ? xv : log1pf(expf(xv));
    float Av = -expf(A_log[(l * 2 + dir) * NHEADS + h]);
    g_dt[dir][r] = dt;
    g_dA[dir][r] = expf(dt * Av);
}

// ---------------- scan phase A: chunk-local scan (h0=0) -------------------
// grid: 1024 = dir*512 + b*256 + h*16 + chunk; 64 threads (p)
__global__ void __launch_bounds__(64) scanA_k(const float* __restrict__ Dp, int l)
{
    int bid = blockIdx.x;
    int chunk = bid & 15;
    int h = (bid >> 4) & 15;
    int b = (bid >> 8) & 1;
    int dir = bid >> 9;
    int p = threadIdx.x;
    const float* xbc = g_xbc[dir];
    const float* dtp = g_dt[dir];
    const float* dAp = g_dA[dir];
    float* yo = g_y[dir];
    float* cAo = g_cA[dir];
    const float Dv = Dp[(l * 2 + dir) * NHEADS + h];
    float hs[16];
    #pragma unroll
    for (int n = 0; n < 16; n++) hs[n] = 0.f;
    float cumA = 1.f;
    __shared__ float sB[8][16], sC[8][16], sdt[8], sdA[8];

    for (int t8 = 0; t8 < CL; t8 += 8) {
        int tb = chunk * CL + t8;
        #pragma unroll
        for (int i = p; i < 128; i += 64) {
            int tt = i >> 4, n = i & 15;
            int o = dir ? (SEQ - 1 - (tb + tt)) : (tb + tt);
            long base = (long)(b * SEQ + o) * CONVDIM + DINNER;
            sB[tt][n] = xbc[base + n];
            sC[tt][n] = xbc[base + DSTATE + n];
        }
        if (p < 8) {
            int o = dir ? (SEQ - 1 - (tb + p)) : (tb + p);
            sdt[p] = dtp[(long)(b * SEQ + o) * NHEADS + h];
            sdA[p] = dAp[(long)(b * SEQ + o) * NHEADS + h];
        }
        __syncthreads();

        float xt[8];
        int oidx[8];
        #pragma unroll
        for (int j = 0; j < 8; j++) {
            int o = dir ? (SEQ - 1 - (tb + j)) : (tb + j);
            oidx[j] = o;
            xt[j] = xbc[(long)(b * SEQ + o) * CONVDIM + h * HEADDIM + p];
        }
        #pragma unroll
        for (int j = 0; j < 8; j++) {
            float dt = sdt[j], dA = sdA[j];
            float cdt = dt * xt[j];
            float y = 0.f;
            #pragma unroll
            for (int n = 0; n < 16; n++) {
                hs[n] = hs[n] * dA + cdt * sB[j][n];
                y += hs[n] * sC[j][n];
            }
            y += Dv * xt[j];
            yo[(long)(b * SEQ + oidx[j]) * DINNER + h * HEADDIM + p] = y;  // pre-gate
            cumA *= dA;
            if (p == 0) cAo[((long)(b * SEQ) + tb + j) * NHEADS + h] = cumA;
        }
        __syncthreads();
    }
    long sbase = ((((long)(dir * 2 + b) * 16 + h) * CH + chunk) * 64 + p) * 16;
    #pragma unroll
    for (int n = 0; n < 16; n++) g_S[sbase + n] = hs[n];
}

// ---------------- scan phase B: sequential chunk combine -------------------
// grid: 64 = dir*32 + b*16 + h; 64 threads (p)
__global__ void __launch_bounds__(64) scanB_k()
{
    int bid = blockIdx.x;
    int h = bid & 15;
    int b = (bid >> 4) & 1;
    int dir = bid >> 5;
    int p = threadIdx.x;
    const float* cAo = g_cA[dir];
    float H[16];
    #pragma unroll
    for (int n = 0; n < 16; n++) H[n] = 0.f;
    for (int c = 0; c < CH; c++) {
        long base = ((((long)(dir * 2 + b) * 16 + h) * CH + c) * 64 + p) * 16;
        #pragma unroll
        for (int n = 0; n < 16; n++) g_Hc[base + n] = H[n];
        float P = cAo[((long)(b * SEQ) + c * CL + CL - 1) * NHEADS + h];
        #pragma unroll
        for (int n = 0; n < 16; n++) H[n] = P * H[n] + g_S[base + n];
    }
}

// ---------------- scan phase C: fixup + gate ----------------
// grid: 1024 like phase A; 64 threads (p)
__global__ void __launch_bounds__(64) scanC_k(int l)
{
    int bid = blockIdx.x;
    int chunk = bid & 15;
    int h = (bid >> 4) & 15;
    int b = (bid >> 8) & 1;
    int dir = bid >> 9;
    int p = threadIdx.x;
    const float* xbc = g_xbc[dir];
    const float* zx = g_zx[dir];
    const float* cAo = g_cA[dir];
    float* yo = g_y[dir];
    float H[16];
    long hbase = ((((long)(dir * 2 + b) * 16 + h) * CH + chunk) * 64 + p) * 16;
    #pragma unroll
    for (int n = 0; n < 16; n++) H[n] = g_Hc[hbase + n];
    __shared__ float sC[8][16], scA[8];

    for (int t8 = 0; t8 < CL; t8 += 8) {
        int tb = chunk * CL + t8;
        #pragma unroll
        for (int i = p; i < 128; i += 64) {
            int tt = i >> 4, n = i & 15;
            int o = dir ? (SEQ - 1 - (tb + tt)) : (tb + tt);
            sC[tt][n] = xbc[(long)(b * SEQ + o) * CONVDIM + DINNER + DSTATE + n];
        }
        if (p < 8)
            scA[p] = cAo[((long)(b * SEQ) + tb + p) * NHEADS + h];
        __syncthreads();

        float yp[8], zt[8];
        int oidx[8];
        #pragma unroll
        for (int j = 0; j < 8; j++) {
            int o = dir ? (SEQ - 1 - (tb + j)) : (tb + j);
            oidx[j] = o;
            yp[j] = yo[(long)(b * SEQ + o) * DINNER + h * HEADDIM + p];
            zt[j] = zx[(long)(b * SEQ + o) * DINPROJ + h * HEADDIM + p];
        }
        #pragma unroll
        for (int j = 0; j < 8; j++) {
            float dot = 0.f;
            #pragma unroll
            for (int n = 0; n < 16; n++) dot += H[n] * sC[j][n];
            float y = yp[j] + scA[j] * dot;
            float z = zt[j];
            float sil = z / (1.f + expf(-z));
            yo[(long)(b * SEQ + oidx[j]) * DINNER + h * HEADDIM + p] = y * sil;
        }
        __syncthreads();
    }
}

// ---------------- RMS norm (1024) -> bf16 hi/lo ----------------
__global__ void __launch_bounds__(256) rms_hl_k(const float* __restrict__ normw, int l)
{
    __shared__ float sbuf[8];
    int bid = blockIdx.x;
    int dir = bid >> 11;
    int tok = bid & (NTOK - 1);
    int tid = threadIdx.x;
    const float* v = g_y[dir] + (long)tok * DINNER;
    const float* w = normw + (l * 2 + dir) * DINNER;
    float vals[4];
    float ss = 0.f;
    #pragma unroll
    for (int i = 0; i < 4; i++) {
        vals[i] = v[tid + i * 256];
        ss += vals[i] * vals[i];
    }
    ss = warpSum(ss);
    if ((tid & 31) == 0) sbuf[tid >> 5] = ss;
    __syncthreads();
    float tot = 0.f;
    #pragma unroll
    for (int i = 0; i < 8; i++) tot += sbuf[i];
    float rs = rsqrtf(tot * (1.f / DINNER) + EPSF);
    #pragma unroll
    for (int i = 0; i < 4; i++) {
        float sv = vals[i] * rs * w[tid + i * 256];
        __nv_bfloat16 h, l2;
        cvt_hl(sv, h, l2);
        long o = (long)tok * DINNER + tid + i * 256;
        g_yh[dir][o] = h;
        g_yl[dir][o] = l2;
    }
}

// ---------------- h += ytmp0 + ytmp1 ----------------
__global__ void __launch_bounds__(256) addres_k()
{
    int i = blockIdx.x * 256 + threadIdx.x;
    if (i < NTOK * DMODEL)
        g_h[i] += g_ytmp[0][i] + g_ytmp[1][i];
}

// ---------------- copy final h into d_out tail ----------------
__global__ void __launch_bounds__(256) copy_hfin_k(float* __restrict__ out)
{
    int i = blockIdx.x * 256 + threadIdx.x;
    if (i < NTOK * DMODEL) out[i] = g_hfin[i];
}

// ---------------- launch ----------------
extern "C" void kernel_launch(void* const* d_in, const int* in_sizes, int n_in,
                              void* d_out, int out_size)
{
    const float* x      = (const float*)d_in[0];
    const float* Wpi    = (const float*)d_in[1];
    const float* bpi    = (const float*)d_in[2];
    const float* ln_w   = (const float*)d_in[3];
    const float* ln_b   = (const float*)d_in[4];
    const float* Win    = (const float*)d_in[5];
    const float* convw  = (const float*)d_in[6];
    const float* convb  = (const float*)d_in[7];
    const float* dt_bias= (const float*)d_in[8];
    const float* A_log  = (const float*)d_in[9];
    const float* Dp     = (const float*)d_in[10];
    const float* normw  = (const float*)d_in[11];
    const float* Wout   = (const float*)d_in[12];
    const float* fn_w   = (const float*)d_in[13];
    const float* fn_b   = (const float*)d_in[14];
    const float* Wpo    = (const float*)d_in[15];
    const float* bpo    = (const float*)d_in[16];
    float* out = (float*)d_out;

    cudaFuncSetAttribute(gemm5<false, true>,  cudaFuncAttributeMaxDynamicSharedMemorySize, GSMEM);
    cudaFuncSetAttribute(gemm5<false, false>, cudaFuncAttributeMaxDynamicSharedMemorySize, GSMEM);

    float *ph, *phf, *pzx, *pyt;
    __nv_bfloat16 *pxh, *pxl, *phnh, *phnl, *pyh, *pyl, *phfh, *phfl;
    __nv_bfloat16 *pwinh, *pwinl, *pwouth, *pwoutl, *pwpih, *pwpil, *pwpoh, *pwpol;
    cudaGetSymbolAddress((void**)&ph,     g_h);
    cudaGetSymbolAddress((void**)&phf,    g_hfin);
    cudaGetSymbolAddress((void**)&pzx,    g_zx);
    cudaGetSymbolAddress((void**)&pyt,    g_ytmp);
    cudaGetSymbolAddress((void**)&pxh,    g_xh);
    cudaGetSymbolAddress((void**)&pxl,    g_xl);
    cudaGetSymbolAddress((void**)&phnh,   g_hnh);
    cudaGetSymbolAddress((void**)&phnl,   g_hnl);
    cudaGetSymbolAddress((void**)&pyh,    g_yh);
    cudaGetSymbolAddress((void**)&pyl,    g_yl);
    cudaGetSymbolAddress((void**)&phfh,   g_hfh);
    cudaGetSymbolAddress((void**)&phfl,   g_hfl);
    cudaGetSymbolAddress((void**)&pwinh,  g_winh);
    cudaGetSymbolAddress((void**)&pwinl,  g_winl);
    cudaGetSymbolAddress((void**)&pwouth, g_wouth);
    cudaGetSymbolAddress((void**)&pwoutl, g_woutl);
    cudaGetSymbolAddress((void**)&pwpih,  g_wpih);
    cudaGetSymbolAddress((void**)&pwpil,  g_wpil);
    cudaGetSymbolAddress((void**)&pwpoh,  g_wpoh);
    cudaGetSymbolAddress((void**)&pwpol,  g_wpol);

    // ---- weight prep ----
    cvt_w_k<<<dim3((KPI*DMODEL + 255)/256, 1, 1), 256>>>(Wpi, pwpih, pwpil, FEAT, DMODEL, KPI, 0, 0);
    cvt_w_k<<<dim3((DMODEL*DINPROJ + 255)/256, 1, 4), 256>>>(
        Win, pwinh, pwinl, DMODEL, DINPROJ, DMODEL,
        (long)DMODEL * DINPROJ, (long)DMODEL * DINPROJ);
    cvt_w_k<<<dim3((DINNER*DMODEL + 255)/256, 1, 4), 256>>>(
        Wout, pwouth, pwoutl, DINNER, DMODEL, DINNER,
        (long)DINNER * DMODEL, (long)DINNER * DMODEL);
    cvt_w_k<<<dim3((DMODEL*FEAT + 255)/256, 1, 1), 256>>>(Wpo, pwpoh, pwpol, DMODEL, FEAT, DMODEL, 0, 0);

    // ---- input proj: h = x @ Wpi + bpi (K padded to 128) ----
    cvt_x_k<<<(NTOK*KPI + 255)/256, 256>>>(x);
    gemm5<false, true><<<dim3(4, 16, 1), 256, GSMEM>>>(
        pxh, pxl, pwpih, pwpil, bpi, ph, DMODEL, KPI, 0, 0, 0);

    for (int l = 0; l < 2; l++) {
        layernorm_hl_k<<<NTOK, 256>>>(ph, ln_w + l*DMODEL, ln_b + l*DMODEL, phnh, phnl, nullptr);
        gemm5<false, false><<<dim3(17, 16, 2), 256, GSMEM>>>(
            phnh, phnl,
            pwinh + (long)l*2*DMODEL*DINPROJ, pwinl + (long)l*2*DMODEL*DINPROJ,
            nullptr, pzx, DINPROJ, DMODEL,
            0, (long)DMODEL*DINPROJ, (long)NTOK*DINPROJ);
        conv_silu_k<<<dim3(9, SEQ, 4), 128>>>(convw, convb, l);
        dtprep_k<<<(2*NTOK*NHEADS + 255)/256, 256>>>(dt_bias, A_log, l);
        scanA_k<<<1024, 64>>>(Dp, l);
        scanB_k<<<64, 64>>>();
        scanC_k<<<1024, 64>>>(l);
        rms_hl_k<<<2*NTOK, 256>>>(normw, l);
        // ytmp[dir] = y[dir] @ Wout[l,dir] (batched), then h += ytmp0+ytmp1
        gemm5<false, false><<<dim3(4, 16, 2), 256, GSMEM>>>(
            pyh, pyl,
            pwouth + (long)l*2*DINNER*DMODEL, pwoutl + (long)l*2*DINNER*DMODEL,
            nullptr, pyt, DMODEL, DINNER,
            (long)NTOK*DINNER, (long)DINNER*DMODEL, (long)NTOK*DMODEL);
        addres_k<<<(NTOK*DMODEL + 255)/256, 256>>>();
    }

    layernorm_hl_k<<<NTOK, 256>>>(ph, fn_w, fn_b, phfh, phfl, phf);
    gemm5<false, true><<<dim3(1, 16, 1), 256, GSMEM>>>(
        phfh, phfl, pwpoh, pwpol, bpo, out, FEAT, DMODEL, 0, 0, 0);
    copy_hfin_k<<<(NTOK*DMODEL + 255)/256, 256>>>(out + (long)NTOK*FEAT);
}